// round 9
// baseline (speedup 1.0000x reference)
#include <cuda_runtime.h>
#include <cstdint>

// Exact analytical collapse of the reference (bit-exact since R1):
//   post-attention LIF can never spike (v'=(v+x)/2 < 1 strictly, x<=1)
//   -> all-zero spikes -> pw@0 = 0 -> BN(0) = p_beta[c] broadcast over
//   [T=4, B=2, C=128, 8*32*32=8192].
//
// R5: route the 33.5MB write through TMA bulk stores instead of STG.
// STG path capped at ~4.3 TB/s across two launch shapes (L2=37% both);
// cp.async.bulk rides the TMA engines -> LTS directly (~6300 B/cyc cap,
// path-independent per B300 microarch measurements).
//
// 1024 planes x 32KB. One block per plane: fill 32KB smem with the
// channel value, one bulk store, retire on read-completion.

static constexpr int PLANES       = 1024;     // T*B*C
static constexpr int PLANE_FLOATS = 8192;     // 8*32*32
static constexpr int PLANE_BYTES  = PLANE_FLOATS * 4;  // 32 KB
static constexpr int THREADS      = 256;

__global__ __launch_bounds__(THREADS)
void bisda_tma_broadcast(const float* __restrict__ p_beta,
                         float* __restrict__ out) {
    __shared__ __align__(128) float buf[PLANE_FLOATS];

    const int p = blockIdx.x;                 // plane index
    const float v = __ldg(p_beta + (p & 127));
    const float4 v4 = make_float4(v, v, v, v);

    float4* b4 = reinterpret_cast<float4*>(buf);
#pragma unroll
    for (int k = 0; k < PLANE_FLOATS / 4 / THREADS; ++k)   // 8 x STS.128
        b4[threadIdx.x + k * THREADS] = v4;
    __syncthreads();

    if (threadIdx.x == 0) {
        // Make generic-proxy smem writes visible to the async (TMA) proxy.
        asm volatile("fence.proxy.async.shared::cta;" ::: "memory");

        uint32_t saddr;
        asm("{ .reg .u64 t; cvta.to.shared.u64 t, %1; cvt.u32.u64 %0, t; }"
            : "=r"(saddr) : "l"(buf));
        uint64_t gaddr = (uint64_t)(out + (size_t)p * PLANE_FLOATS);

        asm volatile(
            "cp.async.bulk.global.shared::cta.bulk_group [%0], [%1], %2;"
            :: "l"(gaddr), "r"(saddr), "n"(PLANE_BYTES) : "memory");
        asm volatile("cp.async.bulk.commit_group;" ::: "memory");
        // Wait only for smem READS to finish (safe to release smem);
        // global writes drain asynchronously after block retirement.
        asm volatile("cp.async.bulk.wait_group.read 0;" ::: "memory");
    }
}

extern "C" void kernel_launch(void* const* d_in, const int* in_sizes, int n_in,
                              void* d_out, int out_size) {
    const float* p_beta = (const float*)d_in[11];
    float* out = (float*)d_out;
    bisda_tma_broadcast<<<PLANES, THREADS>>>(p_beta, out);
}

// round 11
// speedup vs baseline: 1.6632x; 1.6632x over previous
#include <cuda_runtime.h>

// Exact analytical collapse of the reference (bit-exact since R1):
//   post-attention LIF never spikes (v'=(v+x)/2 < 1 strictly for 4 steps,
//   x<=1) -> zero spikes -> pw@0 = 0 -> BN(0) = p_beta[c] broadcast over
//   [T=4, B=2, C=128, 8*32*32]. Output float4 i: c = (i >> 11) & 127.
//
// R10: measured write ceiling ~4.3 TB/s is path-independent (STG == TMA),
// i.e. an LTS write cap. Revert to plain STG (no post-exit drain like TMA),
// balance per-SM bytes via grid-stride with grid = 148*8 blocks, and use
// __stcg to keep stores from occupying L1.

static constexpr int TOTAL_F4 = (4 * 2 * 128 * 8 * 32 * 32) / 4;  // 2,097,152
static constexpr int THREADS  = 256;
static constexpr int BLOCKS   = 148 * 8;                           // 1184

__global__ __launch_bounds__(THREADS)
void bisda_broadcast_beta3(const float* __restrict__ p_beta,
                           float4* __restrict__ out) {
    const int stride = BLOCKS * THREADS;                 // 303,104 threads
    // 2,097,152 / 303,104 = 6.92 -> threads do 7 or 6 stores, extra
    // iterations spread uniformly across SMs (sub-1% per-SM imbalance).
    for (int i = blockIdx.x * THREADS + threadIdx.x; i < TOTAL_F4; i += stride) {
        const int c = (i >> 11) & 127;                   // 2048 f4 per plane
        const float v = __ldg(p_beta + c);               // tiny, L1-resident
        __stcg(out + i, make_float4(v, v, v, v));        // STG.128, L2-cached
    }
}

extern "C" void kernel_launch(void* const* d_in, const int* in_sizes, int n_in,
                              void* d_out, int out_size) {
    const float* p_beta = (const float*)d_in[11];
    float4* out = (float4*)d_out;
    bisda_broadcast_beta3<<<BLOCKS, THREADS>>>(p_beta, out);
}